// round 15
// baseline (speedup 1.0000x reference)
#include <cuda_runtime.h>
#include <cuda_bf16.h>
#include <mma.h>
#include <math.h>
#include <stdint.h>

using namespace nvcuda;

#define NTOK 401408
#define CDIM 96
#define NQKV 288
#define NHID 384
#define HW 224

// ---- scratch (device globals: allocation-free) ----
__device__ float g_qkv[(size_t)NTOK * NQKV];          // fp32 (attn input)
__device__ __nv_bfloat16 g_ahi[(size_t)NTOK * CDIM];  // attn out planes
__device__ __nv_bfloat16 g_alo[(size_t)NTOK * CDIM];
__device__ __nv_bfloat16 g_hhi[(size_t)NTOK * NHID];  // hidden planes
__device__ __nv_bfloat16 g_hlo[(size_t)NTOK * NHID];
// weight planes
__device__ __nv_bfloat16 g_wqh[96 * NQKV], g_wql[96 * NQKV];
__device__ __nv_bfloat16 g_w1h[96 * NHID], g_w1l[96 * NHID];
__device__ __nv_bfloat16 g_w2h[NHID * 96], g_w2l[NHID * 96];

typedef unsigned long long u64t;

__device__ __forceinline__ u64t pk2f(float a, float b){
    u64t r; asm("mov.b64 %0, {%1,%2};" : "=l"(r) : "f"(a), "f"(b)); return r;
}
__device__ __forceinline__ u64t fma2f(u64t a, u64t b, u64t c){
    u64t d; asm("fma.rn.f32x2 %0, %1, %2, %3;" : "=l"(d) : "l"(a), "l"(b), "l"(c)); return d;
}
__device__ __forceinline__ void up2f(u64t x, float& l, float& h){
    asm("mov.b64 {%0,%1}, %2;" : "=f"(l), "=f"(h) : "l"(x));
}

__device__ __forceinline__ void bfsplit(float v, __nv_bfloat16& h, __nv_bfloat16& l) {
    h = __float2bfloat16(v);
    l = __float2bfloat16(v - __bfloat162float(h));
}
__device__ __forceinline__ uint32_t packbf(__nv_bfloat16 a, __nv_bfloat16 b) {
    return ((uint32_t)__bfloat16_as_ushort(b) << 16) | (uint32_t)__bfloat16_as_ushort(a);
}
__device__ __forceinline__ float2 bf2f2(uint32_t u) {
    __nv_bfloat162 t = *reinterpret_cast<__nv_bfloat162*>(&u);
    return __bfloat1622float2(t);
}

// ======================= GEMM smem layout ================================
#define LDA 104
#define LDB 104
#define STG2 52      /* half-width stage ld (48 cols + pad) */
#define STG 100
#define OFF_AHI 0
#define OFF_ALO 26624
#define OFF_BHI 53248
#define OFF_BLO 73216
#define GEMM_SMEM_BYTES 93184

typedef wmma::fragment<wmma::matrix_a, 16, 16, 16, __nv_bfloat16, wmma::row_major> FragA;
typedef wmma::fragment<wmma::matrix_b, 16, 16, 16, __nv_bfloat16, wmma::row_major> FragB;
typedef wmma::fragment<wmma::accumulator, 16, 16, 16, float> FragC;

// copy 128x96 A tile from bf16 planes (row stride rstr elems)
__device__ __forceinline__ void copy_A(const __nv_bfloat16* hi, const __nv_bfloat16* lo,
                                       size_t rstr, __nv_bfloat16* Ahi, __nv_bfloat16* Alo,
                                       int tid) {
    for (int i = tid; i < 128 * 12; i += 256) {
        int r = i / 12, c8 = (i - (i / 12) * 12) * 8;
        *(uint4*)(Ahi + r * LDA + c8) = *(const uint4*)(hi + (size_t)r * rstr + c8);
        *(uint4*)(Alo + r * LDA + c8) = *(const uint4*)(lo + (size_t)r * rstr + c8);
    }
}
// copy 96x96 B tile from bf16 weight planes (row stride bstr elems)
__device__ __forceinline__ void copy_B(const __nv_bfloat16* hi, const __nv_bfloat16* lo,
                                       size_t bstr, __nv_bfloat16* Bhi, __nv_bfloat16* Blo,
                                       int tid) {
    for (int i = tid; i < 96 * 12; i += 256) {
        int k = i / 12, c8 = (i - (i / 12) * 12) * 8;
        *(uint4*)(Bhi + k * LDB + c8) = *(const uint4*)(hi + (size_t)k * bstr + c8);
        *(uint4*)(Blo + k * LDB + c8) = *(const uint4*)(lo + (size_t)k * bstr + c8);
    }
}

// one K=96 split-accumulate pass set: (Ahi,Bhi), (Ahi,Blo), (Alo,Bhi)
__device__ __forceinline__ void mma_chunk(const __nv_bfloat16* Ahi, const __nv_bfloat16* Alo,
                                          const __nv_bfloat16* Bhi, const __nv_bfloat16* Blo,
                                          int wr, int wc, FragC acc[2][3]) {
    #pragma unroll 1
    for (int s = 0; s < 3; s++) {
        const __nv_bfloat16* Ab = (s == 2) ? Alo : Ahi;
        const __nv_bfloat16* Bb = (s == 1) ? Blo : Bhi;
        #pragma unroll 1
        for (int kt = 0; kt < 6; kt++) {
            FragA af[2];
            wmma::load_matrix_sync(af[0], Ab + (wr * 32) * LDA + kt * 16, LDA);
            wmma::load_matrix_sync(af[1], Ab + (wr * 32 + 16) * LDA + kt * 16, LDA);
            #pragma unroll
            for (int ni = 0; ni < 3; ni++) {
                FragB bf;
                wmma::load_matrix_sync(bf, Bb + (kt * 16) * LDB + wc * 48 + ni * 16, LDB);
                wmma::mma_sync(acc[0][ni], af[0], bf, acc[0][ni]);
                wmma::mma_sync(acc[1][ni], af[1], bf, acc[1][ni]);
            }
        }
    }
}

// ======================= 0) weight split ==================================
#define WCONV_TOTAL (96*NQKV + 96*NHID + NHID*96)
__global__ __launch_bounds__(256) void wconv(const float* __restrict__ qkv_w,
                                             const float* __restrict__ w1,
                                             const float* __restrict__ w2) {
    int i = blockIdx.x * 256 + threadIdx.x;
    if (i < 96 * NQKV) {
        bfsplit(qkv_w[i], g_wqh[i], g_wql[i]);
    } else if (i < 96 * NQKV + 96 * NHID) {
        int j = i - 96 * NQKV;
        bfsplit(w1[j], g_w1h[j], g_w1l[j]);
    } else if (i < WCONV_TOTAL) {
        int j = i - 96 * NQKV - 96 * NHID;
        bfsplit(w2[j], g_w2h[j], g_w2l[j]);
    }
}

// ======================= 1+2) fused LN + QKV GEMM =========================
__global__ __launch_bounds__(256) void qkv_gemm(const float* __restrict__ x,
                                                const float* __restrict__ lw,
                                                const float* __restrict__ lb) {
    extern __shared__ __align__(16) char smraw[];
    __nv_bfloat16* Ahi = (__nv_bfloat16*)(smraw + OFF_AHI);
    __nv_bfloat16* Alo = (__nv_bfloat16*)(smraw + OFF_ALO);
    __nv_bfloat16* Bhi = (__nv_bfloat16*)(smraw + OFF_BHI);
    __nv_bfloat16* Blo = (__nv_bfloat16*)(smraw + OFF_BLO);
    const int tid = threadIdx.x;
    const int mt = blockIdx.x;
    const int wid = tid >> 5, lane = tid & 31, wr = wid >> 1, wc = wid & 1;

    // --- fused LayerNorm: warp per row; split straight into A smem tiles ---
    {
        const float lw0 = lw[lane], lw1 = lw[lane + 32], lw2 = lw[lane + 64];
        const float lb0 = lb[lane], lb1 = lb[lane + 32], lb2 = lb[lane + 64];
        for (int r = wid; r < 128; r += 8) {
            const float* xp = x + ((size_t)(mt * 128) + r) * CDIM;
            float a0 = xp[lane], a1 = xp[lane + 32], a2 = xp[lane + 64];
            float sum = a0 + a1 + a2;
            float sq  = a0*a0 + a1*a1 + a2*a2;
            #pragma unroll
            for (int o = 16; o; o >>= 1) {
                sum += __shfl_xor_sync(0xffffffffu, sum, o);
                sq  += __shfl_xor_sync(0xffffffffu, sq , o);
            }
            float mu = sum * (1.f/96.f);
            float var = fmaxf(sq * (1.f/96.f) - mu*mu, 0.f);
            float rs = rsqrtf(var + 1e-5f);
            float y0 = (a0 - mu) * rs * lw0 + lb0;
            float y1 = (a1 - mu) * rs * lw1 + lb1;
            float y2 = (a2 - mu) * rs * lw2 + lb2;
            __nv_bfloat16 h, l;
            bfsplit(y0, h, l); Ahi[r * LDA + lane]      = h; Alo[r * LDA + lane]      = l;
            bfsplit(y1, h, l); Ahi[r * LDA + lane + 32] = h; Alo[r * LDA + lane + 32] = l;
            bfsplit(y2, h, l); Ahi[r * LDA + lane + 64] = h; Alo[r * LDA + lane + 64] = l;
        }
    }

    #pragma unroll 1
    for (int y = 0; y < 3; y++) {
        copy_B(g_wqh + y * 96, g_wql + y * 96, NQKV, Bhi, Blo, tid);
        __syncthreads();   // publishes LN fill (y=0) + B tile
        FragC acc[2][3];
        #pragma unroll
        for (int mi = 0; mi < 2; mi++)
            #pragma unroll
            for (int ni = 0; ni < 3; ni++) wmma::fill_fragment(acc[mi][ni], 0.f);
        mma_chunk(Ahi, Alo, Bhi, Blo, wr, wc, acc);
        float* dbase = g_qkv + (size_t)(mt * 128) * NQKV + y * 96;
        #pragma unroll
        for (int mi = 0; mi < 2; mi++)
            #pragma unroll
            for (int ni = 0; ni < 3; ni++)
                wmma::store_matrix_sync(dbase + (size_t)(wr * 32 + mi * 16) * NQKV + wc * 48 + ni * 16,
                                        acc[mi][ni], NQKV, wmma::mem_row_major);
        __syncthreads();
    }
}

// ======================= 4) MLP1 GEMM + GELU (A once, loop N) =============
__global__ __launch_bounds__(256) void mlp1_gemm(const float* __restrict__ b1) {
    extern __shared__ __align__(16) char smraw[];
    __nv_bfloat16* Ahi = (__nv_bfloat16*)(smraw + OFF_AHI);
    __nv_bfloat16* Alo = (__nv_bfloat16*)(smraw + OFF_ALO);
    __nv_bfloat16* Bhi = (__nv_bfloat16*)(smraw + OFF_BHI);
    __nv_bfloat16* Blo = (__nv_bfloat16*)(smraw + OFF_BLO);
    float* stage = (float*)(smraw + OFF_BHI);   // overlays B (dead post-mma)
    const int tid = threadIdx.x;
    const int mt = blockIdx.x;
    const int wid = tid >> 5, wr = wid >> 1, wc = wid & 1;

    copy_A(g_ahi + (size_t)mt * 128 * CDIM, g_alo + (size_t)mt * 128 * CDIM, CDIM, Ahi, Alo, tid);

    #pragma unroll 1
    for (int y = 0; y < 4; y++) {
        copy_B(g_w1h + y * 96, g_w1l + y * 96, NHID, Bhi, Blo, tid);
        __syncthreads();
        FragC acc[2][3];
        #pragma unroll
        for (int mi = 0; mi < 2; mi++)
            #pragma unroll
            for (int ni = 0; ni < 3; ni++) wmma::fill_fragment(acc[mi][ni], 0.f);
        mma_chunk(Ahi, Alo, Bhi, Blo, wr, wc, acc);
        __syncthreads();   // B dead -> stage
        #pragma unroll 1
        for (int half = 0; half < 2; half++) {
            if (wc == half) {
                #pragma unroll
                for (int mi = 0; mi < 2; mi++)
                    #pragma unroll
                    for (int ni = 0; ni < 3; ni++)
                        wmma::store_matrix_sync(stage + (wr * 32 + mi * 16) * STG2 + ni * 16,
                                                acc[mi][ni], STG2, wmma::mem_row_major);
            }
            __syncthreads();
            const float* bp = b1 + y * 96 + half * 48;
            for (int i = tid; i < 128 * 12; i += 256) {
                int r = i / 12, c4 = (i - (i / 12) * 12) * 4;
                float4 v = *(float4*)(stage + r * STG2 + c4);
                float g0, g1, g2, g3, h;
                h = v.x + bp[c4];     g0 = 0.5f * h * (1.f + erff(h * 0.70710678118654752f));
                h = v.y + bp[c4 + 1]; g1 = 0.5f * h * (1.f + erff(h * 0.70710678118654752f));
                h = v.z + bp[c4 + 2]; g2 = 0.5f * h * (1.f + erff(h * 0.70710678118654752f));
                h = v.w + bp[c4 + 3]; g3 = 0.5f * h * (1.f + erff(h * 0.70710678118654752f));
                __nv_bfloat16 h0,l0,h1,l1,h2,l2,h3,l3;
                bfsplit(g0, h0, l0); bfsplit(g1, h1, l1);
                bfsplit(g2, h2, l2); bfsplit(g3, h3, l3);
                size_t off = (size_t)(mt * 128 + r) * NHID + y * 96 + half * 48 + c4;
                *(uint2*)(g_hhi + off) = make_uint2(packbf(h0, h1), packbf(h2, h3));
                *(uint2*)(g_hlo + off) = make_uint2(packbf(l0, l1), packbf(l2, l3));
            }
            __syncthreads();
        }
    }
}

// ======================= 5) MLP2 GEMM + residual(from planes) =============
__global__ __launch_bounds__(256) void mlp2_gemm(const float* __restrict__ b2,
                                                 float* __restrict__ out) {
    extern __shared__ __align__(16) char smraw[];
    __nv_bfloat16* Ahi = (__nv_bfloat16*)(smraw + OFF_AHI);
    __nv_bfloat16* Alo = (__nv_bfloat16*)(smraw + OFF_ALO);
    __nv_bfloat16* Bhi = (__nv_bfloat16*)(smraw + OFF_BHI);
    __nv_bfloat16* Blo = (__nv_bfloat16*)(smraw + OFF_BLO);
    float* stage = (float*)smraw;     // overlays A (dead after last mma)
    const int tid = threadIdx.x;
    const int mt = blockIdx.x;
    const int wid = tid >> 5, wr = wid >> 1, wc = wid & 1;

    FragC acc[2][3];
    #pragma unroll
    for (int mi = 0; mi < 2; mi++)
        #pragma unroll
        for (int ni = 0; ni < 3; ni++) wmma::fill_fragment(acc[mi][ni], 0.f);

    #pragma unroll 1
    for (int kc = 0; kc < 4; kc++) {
        copy_A(g_hhi + (size_t)mt * 128 * NHID + kc * 96,
               g_hlo + (size_t)mt * 128 * NHID + kc * 96, NHID, Ahi, Alo, tid);
        copy_B(g_w2h + (size_t)(kc * 96) * CDIM, g_w2l + (size_t)(kc * 96) * CDIM,
               CDIM, Bhi, Blo, tid);
        __syncthreads();
        mma_chunk(Ahi, Alo, Bhi, Blo, wr, wc, acc);
        __syncthreads();
    }

    #pragma unroll
    for (int mi = 0; mi < 2; mi++)
        #pragma unroll
        for (int ni = 0; ni < 3; ni++)
            wmma::store_matrix_sync(stage + (wr * 32 + mi * 16) * STG + wc * 48 + ni * 16,
                                    acc[mi][ni], STG, wmma::mem_row_major);
    __syncthreads();

    for (int i = tid; i < 128 * 24; i += 256) {
        int r = i / 24, c4 = (i - (i / 24) * 24) * 4;
        size_t row = (size_t)(mt * 128 + r);
        float4 v = *(float4*)(stage + r * STG + c4);
        uint2 ah = *(const uint2*)(g_ahi + row * CDIM + c4);
        uint2 al = *(const uint2*)(g_alo + row * CDIM + c4);
        float2 h01 = bf2f2(ah.x), h23 = bf2f2(ah.y);
        float2 l01 = bf2f2(al.x), l23 = bf2f2(al.y);
        float4 o;
        o.x = v.x + b2[c4]     + h01.x + l01.x;
        o.y = v.y + b2[c4 + 1] + h01.y + l01.y;
        o.z = v.z + b2[c4 + 2] + h23.x + l23.x;
        o.w = v.w + b2[c4 + 3] + h23.y + l23.y;
        *(float4*)(out + row * CDIM + c4) = o;
    }
}

// ======================= 3) window attention (scalar f32x2) ===============
#define AQ 0
#define AK 4804
#define AV 9608
#define AS 14408
#define ATT_FLOATS (AS + 50*52)          /* 50 S rows: padded row-49 READ */
#define ATT_SMEM_BYTES (ATT_FLOATS * 4)
#define QSTR 98
#define KSTR 98
#define VSTR 96
#define SSTR 52

__global__ __launch_bounds__(256) void attn_kernel() {
    extern __shared__ float sm[];
    float* smQ = sm + AQ;
    float* smK = sm + AK;
    float* smV = sm + AV;
    float* smS = sm + AS;

    const int tid = threadIdx.x;
    const int widx = blockIdx.x;
    const int b  = widx >> 10;
    const int wh = (widx >> 5) & 31;
    const int ww = widx & 31;
    const int base_tok = (b * HW + wh * 7) * HW + ww * 7;

    for (int i = tid; i < 49 * 72; i += 256) {
        int t = i / 72, q = i - t * 72;
        int r = t / 7, s = t - r * 7;
        int tok = base_tok + r * HW + s;
        float4 v = *(const float4*)(g_qkv + (size_t)tok * NQKV + q * 4);
        int j = q * 4;
        float* dst;
        if (j < 96)       dst = smQ + t * QSTR + j;
        else if (j < 192) dst = smK + t * KSTR + (j - 96);
        else              dst = smV + t * VSTR + (j - 192);
        ((u64t*)dst)[0] = pk2f(v.x, v.y);
        ((u64t*)dst)[1] = pk2f(v.z, v.w);
    }
    if (tid < 48) *(u64t*)(smV + 49 * VSTR + tid * 2) = 0ull;
    if (tid < 26) *(u64t*)(smS + 49 * SSTR + tid * 2) = 0ull;
    __syncthreads();

    {
        const float scale = 0.10206207261596577f;
        for (int u = tid; u < 343; u += 256) {
            int n = u / 7, mg = u - n * 7;
            u64t a2[7];
            #pragma unroll
            for (int mm = 0; mm < 7; mm++) a2[mm] = 0ull;
            #pragma unroll 4
            for (int c = 0; c < CDIM; c += 4) {
                const u64t* qp = (const u64t*)(smQ + n * QSTR + c);
                u64t q0 = qp[0], q1 = qp[1];
                #pragma unroll
                for (int mm = 0; mm < 7; mm++) {
                    const u64t* kp = (const u64t*)(smK + (mg * 7 + mm) * KSTR + c);
                    a2[mm] = fma2f(q0, kp[0], a2[mm]);
                    a2[mm] = fma2f(q1, kp[1], a2[mm]);
                }
            }
            #pragma unroll
            for (int mm = 0; mm < 7; mm++) {
                float l, h; up2f(a2[mm], l, h);
                smS[n * SSTR + mg * 7 + mm] = (l + h) * scale;
            }
        }
    }
    __syncthreads();

    {
        const int lane = tid & 31, warp = tid >> 5;
        for (int n = warp; n < 49; n += 8) {
            float v0 = smS[n * SSTR + lane];
            float v1 = (lane < 17) ? smS[n * SSTR + 32 + lane] : -3.0e38f;
            float m = fmaxf(v0, v1);
            #pragma unroll
            for (int o = 16; o; o >>= 1) m = fmaxf(m, __shfl_xor_sync(0xffffffffu, m, o));
            float e0 = __expf(v0 - m);
            float e1 = (lane < 17) ? __expf(v1 - m) : 0.f;
            float ssum = e0 + e1;
            #pragma unroll
            for (int o = 16; o; o >>= 1) ssum += __shfl_xor_sync(0xffffffffu, ssum, o);
            float inv = 1.f / ssum;
            smS[n * SSTR + lane] = e0 * inv;
            if (lane < 17) smS[n * SSTR + 32 + lane] = e1 * inv;
            if (lane == 17) smS[n * SSTR + 49] = 0.f;
        }
    }
    __syncthreads();

    {
        const int cg = tid % 24, tg = tid / 24;
        if (tg < 10) {
            u64t acc[5][4];
            #pragma unroll
            for (int i = 0; i < 5; i++)
                #pragma unroll
                for (int p = 0; p < 4; p++) acc[i][p] = 0ull;
            #pragma unroll 5
            for (int m = 0; m < 50; m += 2) {
                float4 va = *(float4*)(smV + m * VSTR + cg * 4);
                float4 vb = *(float4*)(smV + (m + 1) * VSTR + cg * 4);
                u64t v0 = pk2f(va.x, vb.x), v1 = pk2f(va.y, vb.y);
                u64t v2 = pk2f(va.z, vb.z), v3 = pk2f(va.w, vb.w);
                #pragma unroll
                for (int i = 0; i < 5; i++) {
                    u64t s2 = *(const u64t*)(smS + (tg * 5 + i) * SSTR + m);
                    acc[i][0] = fma2f(s2, v0, acc[i][0]);
                    acc[i][1] = fma2f(s2, v1, acc[i][1]);
                    acc[i][2] = fma2f(s2, v2, acc[i][2]);
                    acc[i][3] = fma2f(s2, v3, acc[i][3]);
                }
            }
            #pragma unroll
            for (int i = 0; i < 5; i++) {
                int t = tg * 5 + i;
                if (t < 49) {
                    int r = t / 7, s = t - r * 7;
                    int tok = base_tok + r * HW + s;
                    float l0,h0,l1,h1,l2,h2,l3,h3;
                    up2f(acc[i][0], l0, h0); up2f(acc[i][1], l1, h1);
                    up2f(acc[i][2], l2, h2); up2f(acc[i][3], l3, h3);
                    float4 o; o.x = l0+h0; o.y = l1+h1; o.z = l2+h2; o.w = l3+h3;
                    size_t off = (size_t)tok * CDIM + cg * 4;
                    __nv_bfloat16 hh0,ll0,hh1,ll1,hh2,ll2,hh3,ll3;
                    bfsplit(o.x, hh0, ll0); bfsplit(o.y, hh1, ll1);
                    bfsplit(o.z, hh2, ll2); bfsplit(o.w, hh3, ll3);
                    *(uint2*)(g_ahi + off) = make_uint2(packbf(hh0, hh1), packbf(hh2, hh3));
                    *(uint2*)(g_alo + off) = make_uint2(packbf(ll0, ll1), packbf(ll2, ll3));
                }
            }
        }
    }
}

// ======================= launcher =========================================
extern "C" void kernel_launch(void* const* d_in, const int* in_sizes, int n_in,
                              void* d_out, int out_size) {
    const float* x     = (const float*)d_in[0];
    const float* qkv_w = (const float*)d_in[1];
    const float* ln_w  = (const float*)d_in[2];
    const float* ln_b  = (const float*)d_in[3];
    const float* w1    = (const float*)d_in[4];
    const float* b1    = (const float*)d_in[5];
    const float* w2    = (const float*)d_in[6];
    const float* b2    = (const float*)d_in[7];
    float* out = (float*)d_out;

    cudaFuncSetAttribute(qkv_gemm,  cudaFuncAttributeMaxDynamicSharedMemorySize, GEMM_SMEM_BYTES);
    cudaFuncSetAttribute(mlp1_gemm, cudaFuncAttributeMaxDynamicSharedMemorySize, GEMM_SMEM_BYTES);
    cudaFuncSetAttribute(mlp2_gemm, cudaFuncAttributeMaxDynamicSharedMemorySize, GEMM_SMEM_BYTES);
    cudaFuncSetAttribute(attn_kernel, cudaFuncAttributeMaxDynamicSharedMemorySize, ATT_SMEM_BYTES);

    wconv<<<(WCONV_TOTAL + 255) / 256, 256>>>(qkv_w, w1, w2);
    qkv_gemm<<<NTOK / 128, 256, GEMM_SMEM_BYTES>>>(x, ln_w, ln_b);
    attn_kernel<<<8192, 256, ATT_SMEM_BYTES>>>();
    mlp1_gemm<<<NTOK / 128, 256, GEMM_SMEM_BYTES>>>(b1);
    mlp2_gemm<<<NTOK / 128, 256, GEMM_SMEM_BYTES>>>(b2, out);
}

// round 17
// speedup vs baseline: 1.0503x; 1.0503x over previous
#include <cuda_runtime.h>
#include <cuda_bf16.h>
#include <mma.h>
#include <math.h>
#include <stdint.h>

using namespace nvcuda;

#define NTOK 401408
#define CDIM 96
#define NQKV 288
#define NHID 384
#define HW 224

// ---- scratch (device globals: allocation-free) ----
__device__ float g_qkv[(size_t)NTOK * NQKV];          // fp32 (attn input)
__device__ __nv_bfloat16 g_ahi[(size_t)NTOK * CDIM];  // attn out planes
__device__ __nv_bfloat16 g_alo[(size_t)NTOK * CDIM];
__device__ __nv_bfloat16 g_hhi[(size_t)NTOK * NHID];  // hidden planes
__device__ __nv_bfloat16 g_hlo[(size_t)NTOK * NHID];
// weight planes
__device__ __nv_bfloat16 g_wqh[96 * NQKV], g_wql[96 * NQKV];
__device__ __nv_bfloat16 g_w1h[96 * NHID], g_w1l[96 * NHID];
__device__ __nv_bfloat16 g_w2h[NHID * 96], g_w2l[NHID * 96];

typedef unsigned long long u64t;

__device__ __forceinline__ u64t pk2f(float a, float b){
    u64t r; asm("mov.b64 %0, {%1,%2};" : "=l"(r) : "f"(a), "f"(b)); return r;
}
__device__ __forceinline__ u64t fma2f(u64t a, u64t b, u64t c){
    u64t d; asm("fma.rn.f32x2 %0, %1, %2, %3;" : "=l"(d) : "l"(a), "l"(b), "l"(c)); return d;
}
__device__ __forceinline__ void up2f(u64t x, float& l, float& h){
    asm("mov.b64 {%0,%1}, %2;" : "=f"(l), "=f"(h) : "l"(x));
}

__device__ __forceinline__ void bfsplit(float v, __nv_bfloat16& h, __nv_bfloat16& l) {
    h = __float2bfloat16(v);
    l = __float2bfloat16(v - __bfloat162float(h));
}
__device__ __forceinline__ uint32_t packbf(__nv_bfloat16 a, __nv_bfloat16 b) {
    return ((uint32_t)__bfloat16_as_ushort(b) << 16) | (uint32_t)__bfloat16_as_ushort(a);
}
__device__ __forceinline__ float2 bf2f2(uint32_t u) {
    __nv_bfloat162 t = *reinterpret_cast<__nv_bfloat162*>(&u);
    return __bfloat1622float2(t);
}

// ======================= GEMM smem layout ================================
#define LDA 104
#define LDB 104
#define STG 100
#define OFF_AHI 0
#define OFF_ALO 26624
#define OFF_BHI 53248
#define OFF_BLO 73216
#define GEMM_SMEM_BYTES 104448   /* B region + 51200B full-width stage overlay */

typedef wmma::fragment<wmma::matrix_a, 16, 16, 16, __nv_bfloat16, wmma::row_major> FragA;
typedef wmma::fragment<wmma::matrix_b, 16, 16, 16, __nv_bfloat16, wmma::row_major> FragB;
typedef wmma::fragment<wmma::accumulator, 16, 16, 16, float> FragC;

// copy 128x96 A tile from bf16 planes (row stride rstr elems)
__device__ __forceinline__ void copy_A(const __nv_bfloat16* hi, const __nv_bfloat16* lo,
                                       size_t rstr, __nv_bfloat16* Ahi, __nv_bfloat16* Alo,
                                       int tid) {
    for (int i = tid; i < 128 * 12; i += 256) {
        int r = i / 12, c8 = (i - (i / 12) * 12) * 8;
        *(uint4*)(Ahi + r * LDA + c8) = *(const uint4*)(hi + (size_t)r * rstr + c8);
        *(uint4*)(Alo + r * LDA + c8) = *(const uint4*)(lo + (size_t)r * rstr + c8);
    }
}
// copy 96x96 B tile from bf16 weight planes (row stride bstr elems)
__device__ __forceinline__ void copy_B(const __nv_bfloat16* hi, const __nv_bfloat16* lo,
                                       size_t bstr, __nv_bfloat16* Bhi, __nv_bfloat16* Blo,
                                       int tid) {
    for (int i = tid; i < 96 * 12; i += 256) {
        int k = i / 12, c8 = (i - (i / 12) * 12) * 8;
        *(uint4*)(Bhi + k * LDB + c8) = *(const uint4*)(hi + (size_t)k * bstr + c8);
        *(uint4*)(Blo + k * LDB + c8) = *(const uint4*)(lo + (size_t)k * bstr + c8);
    }
}

// split-accumulate: (Ahi,Bhi)+(Ahi,Blo) sharing A-frags, then (Alo,Bhi).
__device__ __forceinline__ void mma_chunk(const __nv_bfloat16* Ahi, const __nv_bfloat16* Alo,
                                          const __nv_bfloat16* Bhi, const __nv_bfloat16* Blo,
                                          int wr, int wc, FragC acc[2][3]) {
    #pragma unroll
    for (int kt = 0; kt < 6; kt++) {
        FragA af[2];
        wmma::load_matrix_sync(af[0], Ahi + (wr * 32) * LDA + kt * 16, LDA);
        wmma::load_matrix_sync(af[1], Ahi + (wr * 32 + 16) * LDA + kt * 16, LDA);
        #pragma unroll
        for (int ni = 0; ni < 3; ni++) {
            FragB bf;
            wmma::load_matrix_sync(bf, Bhi + (kt * 16) * LDB + wc * 48 + ni * 16, LDB);
            wmma::mma_sync(acc[0][ni], af[0], bf, acc[0][ni]);
            wmma::mma_sync(acc[1][ni], af[1], bf, acc[1][ni]);
        }
        #pragma unroll
        for (int ni = 0; ni < 3; ni++) {
            FragB bf;
            wmma::load_matrix_sync(bf, Blo + (kt * 16) * LDB + wc * 48 + ni * 16, LDB);
            wmma::mma_sync(acc[0][ni], af[0], bf, acc[0][ni]);
            wmma::mma_sync(acc[1][ni], af[1], bf, acc[1][ni]);
        }
    }
    #pragma unroll
    for (int kt = 0; kt < 6; kt++) {
        FragA af[2];
        wmma::load_matrix_sync(af[0], Alo + (wr * 32) * LDA + kt * 16, LDA);
        wmma::load_matrix_sync(af[1], Alo + (wr * 32 + 16) * LDA + kt * 16, LDA);
        #pragma unroll
        for (int ni = 0; ni < 3; ni++) {
            FragB bf;
            wmma::load_matrix_sync(bf, Bhi + (kt * 16) * LDB + wc * 48 + ni * 16, LDB);
            wmma::mma_sync(acc[0][ni], af[0], bf, acc[0][ni]);
            wmma::mma_sync(acc[1][ni], af[1], bf, acc[1][ni]);
        }
    }
}

// ======================= 0) weight split ==================================
#define WCONV_TOTAL (96*NQKV + 96*NHID + NHID*96)
__global__ __launch_bounds__(256) void wconv(const float* __restrict__ qkv_w,
                                             const float* __restrict__ w1,
                                             const float* __restrict__ w2) {
    int i = blockIdx.x * 256 + threadIdx.x;
    if (i < 96 * NQKV) {
        bfsplit(qkv_w[i], g_wqh[i], g_wql[i]);
    } else if (i < 96 * NQKV + 96 * NHID) {
        int j = i - 96 * NQKV;
        bfsplit(w1[j], g_w1h[j], g_w1l[j]);
    } else if (i < WCONV_TOTAL) {
        int j = i - 96 * NQKV - 96 * NHID;
        bfsplit(w2[j], g_w2h[j], g_w2l[j]);
    }
}

// ======================= 1+2) fused LN + QKV GEMM =========================
__global__ __launch_bounds__(256, 2) void qkv_gemm(const float* __restrict__ x,
                                                   const float* __restrict__ lw,
                                                   const float* __restrict__ lb) {
    extern __shared__ __align__(16) char smraw[];
    __nv_bfloat16* Ahi = (__nv_bfloat16*)(smraw + OFF_AHI);
    __nv_bfloat16* Alo = (__nv_bfloat16*)(smraw + OFF_ALO);
    __nv_bfloat16* Bhi = (__nv_bfloat16*)(smraw + OFF_BHI);
    __nv_bfloat16* Blo = (__nv_bfloat16*)(smraw + OFF_BLO);
    const int tid = threadIdx.x;
    const int mt = blockIdx.x;
    const int wid = tid >> 5, lane = tid & 31, wr = wid >> 1, wc = wid & 1;

    // --- fused LayerNorm: warp per row; split straight into A smem tiles ---
    {
        const float lw0 = lw[lane], lw1 = lw[lane + 32], lw2 = lw[lane + 64];
        const float lb0 = lb[lane], lb1 = lb[lane + 32], lb2 = lb[lane + 64];
        for (int r = wid; r < 128; r += 8) {
            const float* xp = x + ((size_t)(mt * 128) + r) * CDIM;
            float a0 = xp[lane], a1 = xp[lane + 32], a2 = xp[lane + 64];
            float sum = a0 + a1 + a2;
            float sq  = a0*a0 + a1*a1 + a2*a2;
            #pragma unroll
            for (int o = 16; o; o >>= 1) {
                sum += __shfl_xor_sync(0xffffffffu, sum, o);
                sq  += __shfl_xor_sync(0xffffffffu, sq , o);
            }
            float mu = sum * (1.f/96.f);
            float var = fmaxf(sq * (1.f/96.f) - mu*mu, 0.f);
            float rs = rsqrtf(var + 1e-5f);
            float y0 = (a0 - mu) * rs * lw0 + lb0;
            float y1 = (a1 - mu) * rs * lw1 + lb1;
            float y2 = (a2 - mu) * rs * lw2 + lb2;
            __nv_bfloat16 h, l;
            bfsplit(y0, h, l); Ahi[r * LDA + lane]      = h; Alo[r * LDA + lane]      = l;
            bfsplit(y1, h, l); Ahi[r * LDA + lane + 32] = h; Alo[r * LDA + lane + 32] = l;
            bfsplit(y2, h, l); Ahi[r * LDA + lane + 64] = h; Alo[r * LDA + lane + 64] = l;
        }
    }

    #pragma unroll 1
    for (int y = 0; y < 3; y++) {
        copy_B(g_wqh + y * 96, g_wql + y * 96, NQKV, Bhi, Blo, tid);
        __syncthreads();   // publishes LN fill (y=0) + B tile
        FragC acc[2][3];
        #pragma unroll
        for (int mi = 0; mi < 2; mi++)
            #pragma unroll
            for (int ni = 0; ni < 3; ni++) wmma::fill_fragment(acc[mi][ni], 0.f);
        mma_chunk(Ahi, Alo, Bhi, Blo, wr, wc, acc);
        float* dbase = g_qkv + (size_t)(mt * 128) * NQKV + y * 96;
        #pragma unroll
        for (int mi = 0; mi < 2; mi++)
            #pragma unroll
            for (int ni = 0; ni < 3; ni++)
                wmma::store_matrix_sync(dbase + (size_t)(wr * 32 + mi * 16) * NQKV + wc * 48 + ni * 16,
                                        acc[mi][ni], NQKV, wmma::mem_row_major);
        __syncthreads();
    }
}

// ======================= 4) MLP1 GEMM + GELU (A once, loop N) =============
__global__ __launch_bounds__(256, 2) void mlp1_gemm(const float* __restrict__ b1) {
    extern __shared__ __align__(16) char smraw[];
    __nv_bfloat16* Ahi = (__nv_bfloat16*)(smraw + OFF_AHI);
    __nv_bfloat16* Alo = (__nv_bfloat16*)(smraw + OFF_ALO);
    __nv_bfloat16* Bhi = (__nv_bfloat16*)(smraw + OFF_BHI);
    __nv_bfloat16* Blo = (__nv_bfloat16*)(smraw + OFF_BLO);
    float* stage = (float*)(smraw + OFF_BHI);   // full 128x100 f32, overlays B (dead post-mma)
    const int tid = threadIdx.x;
    const int mt = blockIdx.x;
    const int wid = tid >> 5, wr = wid >> 1, wc = wid & 1;

    copy_A(g_ahi + (size_t)mt * 128 * CDIM, g_alo + (size_t)mt * 128 * CDIM, CDIM, Ahi, Alo, tid);

    #pragma unroll 1
    for (int y = 0; y < 4; y++) {
        copy_B(g_w1h + y * 96, g_w1l + y * 96, NHID, Bhi, Blo, tid);
        __syncthreads();
        FragC acc[2][3];
        #pragma unroll
        for (int mi = 0; mi < 2; mi++)
            #pragma unroll
            for (int ni = 0; ni < 3; ni++) wmma::fill_fragment(acc[mi][ni], 0.f);
        mma_chunk(Ahi, Alo, Bhi, Blo, wr, wc, acc);
        __syncthreads();   // B dead -> full stage
        #pragma unroll
        for (int mi = 0; mi < 2; mi++)
            #pragma unroll
            for (int ni = 0; ni < 3; ni++)
                wmma::store_matrix_sync(stage + (wr * 32 + mi * 16) * STG + wc * 48 + ni * 16,
                                        acc[mi][ni], STG, wmma::mem_row_major);
        __syncthreads();
        const float* bp = b1 + y * 96;
        for (int i = tid; i < 128 * 24; i += 256) {
            int r = i / 24, c4 = (i - (i / 24) * 24) * 4;
            float4 v = *(float4*)(stage + r * STG + c4);
            float g0, g1, g2, g3, h;
            h = v.x + bp[c4];     g0 = 0.5f * h * (1.f + erff(h * 0.70710678118654752f));
            h = v.y + bp[c4 + 1]; g1 = 0.5f * h * (1.f + erff(h * 0.70710678118654752f));
            h = v.z + bp[c4 + 2]; g2 = 0.5f * h * (1.f + erff(h * 0.70710678118654752f));
            h = v.w + bp[c4 + 3]; g3 = 0.5f * h * (1.f + erff(h * 0.70710678118654752f));
            __nv_bfloat16 h0,l0,h1,l1,h2,l2,h3,l3;
            bfsplit(g0, h0, l0); bfsplit(g1, h1, l1);
            bfsplit(g2, h2, l2); bfsplit(g3, h3, l3);
            size_t off = (size_t)(mt * 128 + r) * NHID + y * 96 + c4;
            *(uint2*)(g_hhi + off) = make_uint2(packbf(h0, h1), packbf(h2, h3));
            *(uint2*)(g_hlo + off) = make_uint2(packbf(l0, l1), packbf(l2, l3));
        }
        __syncthreads();   // stage consumed before next y's copy_B
    }
}

// ======================= 5) MLP2 GEMM + residual(from planes) =============
__global__ __launch_bounds__(256, 2) void mlp2_gemm(const float* __restrict__ b2,
                                                    float* __restrict__ out) {
    extern __shared__ __align__(16) char smraw[];
    __nv_bfloat16* Ahi = (__nv_bfloat16*)(smraw + OFF_AHI);
    __nv_bfloat16* Alo = (__nv_bfloat16*)(smraw + OFF_ALO);
    __nv_bfloat16* Bhi = (__nv_bfloat16*)(smraw + OFF_BHI);
    __nv_bfloat16* Blo = (__nv_bfloat16*)(smraw + OFF_BLO);
    float* stage = (float*)smraw;     // overlays A (dead after last mma)
    const int tid = threadIdx.x;
    const int mt = blockIdx.x;
    const int wid = tid >> 5, wr = wid >> 1, wc = wid & 1;

    FragC acc[2][3];
    #pragma unroll
    for (int mi = 0; mi < 2; mi++)
        #pragma unroll
        for (int ni = 0; ni < 3; ni++) wmma::fill_fragment(acc[mi][ni], 0.f);

    #pragma unroll 1
    for (int kc = 0; kc < 4; kc++) {
        copy_A(g_hhi + (size_t)mt * 128 * NHID + kc * 96,
               g_hlo + (size_t)mt * 128 * NHID + kc * 96, NHID, Ahi, Alo, tid);
        copy_B(g_w2h + (size_t)(kc * 96) * CDIM, g_w2l + (size_t)(kc * 96) * CDIM,
               CDIM, Bhi, Blo, tid);
        __syncthreads();
        mma_chunk(Ahi, Alo, Bhi, Blo, wr, wc, acc);
        __syncthreads();
    }

    #pragma unroll
    for (int mi = 0; mi < 2; mi++)
        #pragma unroll
        for (int ni = 0; ni < 3; ni++)
            wmma::store_matrix_sync(stage + (wr * 32 + mi * 16) * STG + wc * 48 + ni * 16,
                                    acc[mi][ni], STG, wmma::mem_row_major);
    __syncthreads();

    for (int i = tid; i < 128 * 24; i += 256) {
        int r = i / 24, c4 = (i - (i / 24) * 24) * 4;
        size_t row = (size_t)(mt * 128 + r);
        float4 v = *(float4*)(stage + r * STG + c4);
        uint2 ah = *(const uint2*)(g_ahi + row * CDIM + c4);
        uint2 al = *(const uint2*)(g_alo + row * CDIM + c4);
        float2 h01 = bf2f2(ah.x), h23 = bf2f2(ah.y);
        float2 l01 = bf2f2(al.x), l23 = bf2f2(al.y);
        float4 o;
        o.x = v.x + b2[c4]     + h01.x + l01.x;
        o.y = v.y + b2[c4 + 1] + h01.y + l01.y;
        o.z = v.z + b2[c4 + 2] + h23.x + l23.x;
        o.w = v.w + b2[c4 + 3] + h23.y + l23.y;
        *(float4*)(out + row * CDIM + c4) = o;
    }
}

// ======================= 3) window attention (scalar f32x2) ===============
#define AQ 0
#define AK 4804
#define AV 9608
#define AS 14408
#define ATT_FLOATS (AS + 50*52)          /* 50 S rows: padded row-49 READ */
#define ATT_SMEM_BYTES (ATT_FLOATS * 4)
#define QSTR 98
#define KSTR 98
#define VSTR 96
#define SSTR 52

__global__ __launch_bounds__(256) void attn_kernel() {
    extern __shared__ float sm[];
    float* smQ = sm + AQ;
    float* smK = sm + AK;
    float* smV = sm + AV;
    float* smS = sm + AS;

    const int tid = threadIdx.x;
    const int widx = blockIdx.x;
    const int b  = widx >> 10;
    const int wh = (widx >> 5) & 31;
    const int ww = widx & 31;
    const int base_tok = (b * HW + wh * 7) * HW + ww * 7;

    for (int i = tid; i < 49 * 72; i += 256) {
        int t = i / 72, q = i - t * 72;
        int r = t / 7, s = t - r * 7;
        int tok = base_tok + r * HW + s;
        float4 v = *(const float4*)(g_qkv + (size_t)tok * NQKV + q * 4);
        int j = q * 4;
        float* dst;
        if (j < 96)       dst = smQ + t * QSTR + j;
        else if (j < 192) dst = smK + t * KSTR + (j - 96);
        else              dst = smV + t * VSTR + (j - 192);
        ((u64t*)dst)[0] = pk2f(v.x, v.y);
        ((u64t*)dst)[1] = pk2f(v.z, v.w);
    }
    if (tid < 48) *(u64t*)(smV + 49 * VSTR + tid * 2) = 0ull;
    if (tid < 26) *(u64t*)(smS + 49 * SSTR + tid * 2) = 0ull;
    __syncthreads();

    {
        const float scale = 0.10206207261596577f;
        for (int u = tid; u < 343; u += 256) {
            int n = u / 7, mg = u - n * 7;
            u64t a2[7];
            #pragma unroll
            for (int mm = 0; mm < 7; mm++) a2[mm] = 0ull;
            #pragma unroll 4
            for (int c = 0; c < CDIM; c += 4) {
                const u64t* qp = (const u64t*)(smQ + n * QSTR + c);
                u64t q0 = qp[0], q1 = qp[1];
                #pragma unroll
                for (int mm = 0; mm < 7; mm++) {
                    const u64t* kp = (const u64t*)(smK + (mg * 7 + mm) * KSTR + c);
                    a2[mm] = fma2f(q0, kp[0], a2[mm]);
                    a2[mm] = fma2f(q1, kp[1], a2[mm]);
                }
            }
            #pragma unroll
            for (int mm = 0; mm < 7; mm++) {
                float l, h; up2f(a2[mm], l, h);
                smS[n * SSTR + mg * 7 + mm] = (l + h) * scale;
            }
        }
    }
    __syncthreads();

    {
        const int lane = tid & 31, warp = tid >> 5;
        for (int n = warp; n < 49; n += 8) {
            float v0 = smS[n * SSTR + lane];
            float v1 = (lane < 17) ? smS[n * SSTR + 32 + lane] : -3.0e38f;
            float m = fmaxf(v0, v1);
            #pragma unroll
            for (int o = 16; o; o >>= 1) m = fmaxf(m, __shfl_xor_sync(0xffffffffu, m, o));
            float e0 = __expf(v0 - m);
            float e1 = (lane < 17) ? __expf(v1 - m) : 0.f;
            float ssum = e0 + e1;
            #pragma unroll
            for (int o = 16; o; o >>= 1) ssum += __shfl_xor_sync(0xffffffffu, ssum, o);
            float inv = 1.f / ssum;
            smS[n * SSTR + lane] = e0 * inv;
            if (lane < 17) smS[n * SSTR + 32 + lane] = e1 * inv;
            if (lane == 17) smS[n * SSTR + 49] = 0.f;
        }
    }
    __syncthreads();

    {
        const int cg = tid % 24, tg = tid / 24;
        if (tg < 10) {
            u64t acc[5][4];
            #pragma unroll
            for (int i = 0; i < 5; i++)
                #pragma unroll
                for (int p = 0; p < 4; p++) acc[i][p] = 0ull;
            #pragma unroll 5
            for (int m = 0; m < 50; m += 2) {
                float4 va = *(float4*)(smV + m * VSTR + cg * 4);
                float4 vb = *(float4*)(smV + (m + 1) * VSTR + cg * 4);
                u64t v0 = pk2f(va.x, vb.x), v1 = pk2f(va.y, vb.y);
                u64t v2 = pk2f(va.z, vb.z), v3 = pk2f(va.w, vb.w);
                #pragma unroll
                for (int i = 0; i < 5; i++) {
                    u64t s2 = *(const u64t*)(smS + (tg * 5 + i) * SSTR + m);
                    acc[i][0] = fma2f(s2, v0, acc[i][0]);
                    acc[i][1] = fma2f(s2, v1, acc[i][1]);
                    acc[i][2] = fma2f(s2, v2, acc[i][2]);
                    acc[i][3] = fma2f(s2, v3, acc[i][3]);
                }
            }
            #pragma unroll
            for (int i = 0; i < 5; i++) {
                int t = tg * 5 + i;
                if (t < 49) {
                    int r = t / 7, s = t - r * 7;
                    int tok = base_tok + r * HW + s;
                    float l0,h0,l1,h1,l2,h2,l3,h3;
                    up2f(acc[i][0], l0, h0); up2f(acc[i][1], l1, h1);
                    up2f(acc[i][2], l2, h2); up2f(acc[i][3], l3, h3);
                    float4 o; o.x = l0+h0; o.y = l1+h1; o.z = l2+h2; o.w = l3+h3;
                    size_t off = (size_t)tok * CDIM + cg * 4;
                    __nv_bfloat16 hh0,ll0,hh1,ll1,hh2,ll2,hh3,ll3;
                    bfsplit(o.x, hh0, ll0); bfsplit(o.y, hh1, ll1);
                    bfsplit(o.z, hh2, ll2); bfsplit(o.w, hh3, ll3);
                    *(uint2*)(g_ahi + off) = make_uint2(packbf(hh0, hh1), packbf(hh2, hh3));
                    *(uint2*)(g_alo + off) = make_uint2(packbf(ll0, ll1), packbf(ll2, ll3));
                }
            }
        }
    }
}

// ======================= launcher =========================================
extern "C" void kernel_launch(void* const* d_in, const int* in_sizes, int n_in,
                              void* d_out, int out_size) {
    const float* x     = (const float*)d_in[0];
    const float* qkv_w = (const float*)d_in[1];
    const float* ln_w  = (const float*)d_in[2];
    const float* ln_b  = (const float*)d_in[3];
    const float* w1    = (const float*)d_in[4];
    const float* b1    = (const float*)d_in[5];
    const float* w2    = (const float*)d_in[6];
    const float* b2    = (const float*)d_in[7];
    float* out = (float*)d_out;

    cudaFuncSetAttribute(qkv_gemm,  cudaFuncAttributeMaxDynamicSharedMemorySize, GEMM_SMEM_BYTES);
    cudaFuncSetAttribute(mlp1_gemm, cudaFuncAttributeMaxDynamicSharedMemorySize, GEMM_SMEM_BYTES);
    cudaFuncSetAttribute(mlp2_gemm, cudaFuncAttributeMaxDynamicSharedMemorySize, GEMM_SMEM_BYTES);
    cudaFuncSetAttribute(attn_kernel, cudaFuncAttributeMaxDynamicSharedMemorySize, ATT_SMEM_BYTES);

    wconv<<<(WCONV_TOTAL + 255) / 256, 256>>>(qkv_w, w1, w2);
    qkv_gemm<<<NTOK / 128, 256, GEMM_SMEM_BYTES>>>(x, ln_w, ln_b);
    attn_kernel<<<8192, 256, ATT_SMEM_BYTES>>>();
    mlp1_gemm<<<NTOK / 128, 256, GEMM_SMEM_BYTES>>>(b1);
    mlp2_gemm<<<NTOK / 128, 256, GEMM_SMEM_BYTES>>>(b2, out);
}